// round 3
// baseline (speedup 1.0000x reference)
#include <cuda_runtime.h>
#include <cstdint>

// Problem constants
#define BB 2
#define TT 2048
#define CC 768
#define NH 12
#define HD 64
#define MM (BB*TT)        // 4096 rows
#define C3 (3*CC)         // 2304

// Scratch (allocation-free rule: __device__ globals)
__device__ float g_qkv[(size_t)MM * C3];   // [M, 3C]
__device__ float g_att[(size_t)MM * CC];   // [M, C] attention output (pre-proj)

// ---------------------------------------------------------------------------
// SGEMM: out[M,N] = A[M,K] * W[N,K]^T   (torch-Linear weights, both row-major)
// 128x128 block tile, BK=8, 256 threads, 8x8 register micro-tile,
// double-buffered smem (1 barrier per K-tile), global loads overlapped.
// Requires M%128==0, N%128==0, K%8==0 (holds: 4096, {2304,768}, 768).
// ---------------------------------------------------------------------------
__global__ void __launch_bounds__(256) sgemm128(const float* __restrict__ A,
                                                const float* __restrict__ W,
                                                float* __restrict__ out,
                                                int Ndim, int Kdim)
{
    __shared__ float As[2][8][128];   // As[buf][k][m]
    __shared__ float Bs[2][8][128];   // Bs[buf][k][n]

    const int tid = threadIdx.x;
    const int m0 = blockIdx.y * 128;
    const int n0 = blockIdx.x * 128;

    // Loader mapping: one float4 of A and one of W per thread per K-tile.
    const int lr = tid >> 1;            // 0..127 (row within tile)
    const int lk = (tid & 1) << 2;      // 0 or 4 (K offset)
    const float* Ap = A + (size_t)(m0 + lr) * Kdim + lk;
    const float* Wp = W + (size_t)(n0 + lr) * Kdim + lk;

    // Compute mapping: 16x16 thread grid, 8x8 micro-tile.
    const int tx = (tid & 15) << 3;     // n offset 0..120
    const int ty = (tid >> 4) << 3;     // m offset 0..120

    float acc[8][8] = {};

    const int numTiles = Kdim >> 3;

    // Preload tile 0
    {
        float4 av = *(const float4*)Ap;
        float4 wv = *(const float4*)Wp;
        As[0][lk + 0][lr] = av.x; As[0][lk + 1][lr] = av.y;
        As[0][lk + 2][lr] = av.z; As[0][lk + 3][lr] = av.w;
        Bs[0][lk + 0][lr] = wv.x; Bs[0][lk + 1][lr] = wv.y;
        Bs[0][lk + 2][lr] = wv.z; Bs[0][lk + 3][lr] = wv.w;
    }
    __syncthreads();

    int buf = 0;
    for (int kt = 0; kt < numTiles; kt++) {
        // Fetch next tile's globals into registers (latency hidden by compute)
        float4 av, wv;
        const bool more = (kt + 1) < numTiles;
        if (more) {
            const int k0 = (kt + 1) << 3;
            av = *(const float4*)(Ap + k0);
            wv = *(const float4*)(Wp + k0);
        }

        // Micro-kernel on current buffer
        #pragma unroll
        for (int k = 0; k < 8; k++) {
            float a[8], b[8];
            *(float4*)&a[0] = *(const float4*)&As[buf][k][ty];
            *(float4*)&a[4] = *(const float4*)&As[buf][k][ty + 4];
            *(float4*)&b[0] = *(const float4*)&Bs[buf][k][tx];
            *(float4*)&b[4] = *(const float4*)&Bs[buf][k][tx + 4];
            #pragma unroll
            for (int i = 0; i < 8; i++)
                #pragma unroll
                for (int j = 0; j < 8; j++)
                    acc[i][j] = fmaf(a[i], b[j], acc[i][j]);
        }

        if (more) {
            const int nb = buf ^ 1;
            As[nb][lk + 0][lr] = av.x; As[nb][lk + 1][lr] = av.y;
            As[nb][lk + 2][lr] = av.z; As[nb][lk + 3][lr] = av.w;
            Bs[nb][lk + 0][lr] = wv.x; Bs[nb][lk + 1][lr] = wv.y;
            Bs[nb][lk + 2][lr] = wv.z; Bs[nb][lk + 3][lr] = wv.w;
            __syncthreads();
            buf = nb;
        }
    }

    #pragma unroll
    for (int i = 0; i < 8; i++) {
        float* orow = out + (size_t)(m0 + ty + i) * Ndim + n0 + tx;
        *(float4*)orow       = make_float4(acc[i][0], acc[i][1], acc[i][2], acc[i][3]);
        *(float4*)(orow + 4) = make_float4(acc[i][4], acc[i][5], acc[i][6], acc[i][7]);
    }
}

// ---------------------------------------------------------------------------
// Flash-attention style fused causal attention, fp32.
// Grid: (T/64, H, B). Block: 256 threads. 64-query x 64-key tiles, D=64.
// Online softmax (all 256 threads: 4 lanes/row via shfl.bfly);
// O accumulator in registers (4x4 per thread).
// ---------------------------------------------------------------------------
#define SMEM_FLASH ((4*64*68 + 3*64) * 4)

__global__ void __launch_bounds__(256) flash_attn(const float* __restrict__ qkv,
                                                  float* __restrict__ att)
{
    extern __shared__ float sm[];
    float (*Qt)[68] = (float(*)[68])(sm);               // Qt[d][r]
    float (*Kt)[68] = (float(*)[68])(sm + 64 * 68);     // Kt[d][c]
    float (*Vs)[68] = (float(*)[68])(sm + 2 * 64 * 68); // Vs[c][d]
    float (*St)[68] = (float(*)[68])(sm + 3 * 64 * 68); // St[c][r]  (S transposed)
    float* m_s    = sm + 4 * 64 * 68;
    float* l_s    = m_s + 64;
    float* corr_s = l_s + 64;

    const int tid = threadIdx.x;
    const int tx = tid & 15;      // dim/col micro index
    const int ty = tid >> 4;      // row micro index
    const int qi = blockIdx.x;    // query tile
    const int h  = blockIdx.y;
    const int b  = blockIdx.z;
    const int q0 = qi * 64;
    const float scale = 0.125f;   // 1/sqrt(64)

    // Load Q tile transposed: Qt[d][r]
    for (int e = tid; e < 64 * 64; e += 256) {
        int d = e & 63, r = e >> 6;
        Qt[d][r] = qkv[(size_t)(b * TT + q0 + r) * C3 + h * HD + d];
    }
    if (tid < 64) { m_s[tid] = -1e30f; l_s[tid] = 0.0f; }

    float acc[4][4] = {};
    __syncthreads();

    for (int kt = 0; kt <= qi; kt++) {
        const int kb = kt * 64;
        // Load K (transposed) and V tiles
        for (int e = tid; e < 64 * 64; e += 256) {
            int d = e & 63, c = e >> 6;
            size_t row = (size_t)(b * TT + kb + c) * C3 + h * HD;
            Kt[d][c] = qkv[row + CC + d];
            Vs[c][d] = qkv[row + 2 * CC + d];
        }
        __syncthreads();

        // S = Q @ K^T  (each thread: rows ty*4+i, cols tx*4+j)
        float s[4][4] = {};
        #pragma unroll 16
        for (int k = 0; k < 64; k++) {
            float4 a = *(const float4*)&Qt[k][ty << 2];
            float4 bb = *(const float4*)&Kt[k][tx << 2];
            float ar[4] = {a.x, a.y, a.z, a.w};
            float br[4] = {bb.x, bb.y, bb.z, bb.w};
            #pragma unroll
            for (int i = 0; i < 4; i++)
                #pragma unroll
                for (int j = 0; j < 4; j++)
                    s[i][j] = fmaf(ar[i], br[j], s[i][j]);
        }

        // scale + causal mask, store transposed St[c][r]
        const bool diag = (kt == qi);
        #pragma unroll
        for (int i = 0; i < 4; i++) {
            int rr = (ty << 2) + i;
            #pragma unroll
            for (int j = 0; j < 4; j++) {
                int cc = (tx << 2) + j;
                float v = s[i][j] * scale;
                if (diag && cc > rr) v = -1e30f;
                St[cc][rr] = v;
            }
        }
        __syncthreads();

        // Online softmax: all 256 threads, 4 lanes per row, 16 cols each.
        {
            const int r    = tid >> 2;       // 0..63
            const int part = tid & 3;        // 0..3
            const int c0   = part << 4;      // 0,16,32,48
            float mx = -1e30f;
            #pragma unroll
            for (int c = c0; c < c0 + 16; c++) mx = fmaxf(mx, St[c][r]);
            mx = fmaxf(mx, __shfl_xor_sync(0xFFFFFFFFu, mx, 1));
            mx = fmaxf(mx, __shfl_xor_sync(0xFFFFFFFFu, mx, 2));
            float mo = m_s[r];
            float mn = fmaxf(mo, mx);
            float sum = 0.0f;
            #pragma unroll
            for (int c = c0; c < c0 + 16; c++) {
                float p = __expf(St[c][r] - mn);
                St[c][r] = p;
                sum += p;
            }
            sum += __shfl_xor_sync(0xFFFFFFFFu, sum, 1);
            sum += __shfl_xor_sync(0xFFFFFFFFu, sum, 2);
            if (part == 0) {
                float cr = __expf(mo - mn);
                l_s[r] = l_s[r] * cr + sum;
                m_s[r] = mn;
                corr_s[r] = cr;
            }
        }
        __syncthreads();

        // Rescale O, then O += P @ V
        #pragma unroll
        for (int i = 0; i < 4; i++) {
            float cr = corr_s[(ty << 2) + i];
            #pragma unroll
            for (int j = 0; j < 4; j++) acc[i][j] *= cr;
        }
        #pragma unroll 16
        for (int k = 0; k < 64; k++) {
            float4 a = *(const float4*)&St[k][ty << 2];   // P[r][k] for 4 rows
            float4 bb = *(const float4*)&Vs[k][tx << 2];  // V[k][d] for 4 dims
            float ar[4] = {a.x, a.y, a.z, a.w};
            float br[4] = {bb.x, bb.y, bb.z, bb.w};
            #pragma unroll
            for (int i = 0; i < 4; i++)
                #pragma unroll
                for (int j = 0; j < 4; j++)
                    acc[i][j] = fmaf(ar[i], br[j], acc[i][j]);
        }
        __syncthreads();   // protect smem tiles before next iteration overwrites
    }

    // Normalize and write: att[b*T + q, h*64 + d]
    #pragma unroll
    for (int i = 0; i < 4; i++) {
        float inv = 1.0f / l_s[(ty << 2) + i];
        float4 o = make_float4(acc[i][0] * inv, acc[i][1] * inv,
                               acc[i][2] * inv, acc[i][3] * inv);
        *(float4*)&att[(size_t)(b * TT + q0 + (ty << 2) + i) * CC + h * HD + (tx << 2)] = o;
    }
}

// ---------------------------------------------------------------------------
extern "C" void kernel_launch(void* const* d_in, const int* in_sizes, int n_in,
                              void* d_out, int out_size)
{
    const float* x      = (const float*)d_in[0];   // [B,T,C]
    const float* W_attn = (const float*)d_in[1];   // [3C, C]
    const float* W_proj = (const float*)d_in[2];   // [C, C]
    float* out = (float*)d_out;                    // [B,T,C]

    void* qkv_ptr = nullptr;
    void* att_ptr = nullptr;
    cudaGetSymbolAddress(&qkv_ptr, g_qkv);
    cudaGetSymbolAddress(&att_ptr, g_att);

    cudaFuncSetAttribute(flash_attn, cudaFuncAttributeMaxDynamicSharedMemorySize,
                         SMEM_FLASH);

    // 1) QKV projection: [4096,768] x [2304,768]^T -> [4096,2304]
    sgemm128<<<dim3(C3 / 128, MM / 128), 256>>>(x, W_attn, (float*)qkv_ptr, C3, CC);

    // 2) Fused causal attention -> [4096,768]
    flash_attn<<<dim3(TT / 64, NH, BB), 256, SMEM_FLASH>>>((const float*)qkv_ptr,
                                                           (float*)att_ptr);

    // 3) Output projection: [4096,768] x [768,768]^T -> [4096,768]
    sgemm128<<<dim3(CC / 128, MM / 128), 256>>>((const float*)att_ptr, W_proj, out,
                                                CC, CC);
}